// round 13
// baseline (speedup 1.0000x reference)
#include <cuda_runtime.h>
#include <cuda_fp16.h>

// ---------------------------------------------------------------------------
// GCN: 2x GCNConv (sym-norm, self-loops) + leaky + concat-FC + sigmoid
// R13: identical to R12 except __launch_bounds__(256, 5): cap 51 regs/thread
// -> 5 co-resident CTAs/SM (1280 thr, 62.5% occ, +25% warps) to cover the
// gather latency the extra ILP could no longer hide (L1 55%, issue 29%).
// ---------------------------------------------------------------------------

#define MAXN   100000
#define MAXE   1600000
#define BUCKET 128            // max in-degree per node (Poisson(16): safe)
#define NEG_SLOPE 0.01f

__device__ int      g_cnt[MAXN];            // bucket fill count == in-degree
__device__ int      g_csr[MAXN * BUCKET];   // sources, bucketed by target
__device__ float    g_dinv[MAXN];           // rsqrt(deg+1)
__device__ float4   g_xh [MAXN * 2];        // fp16 dinv*x (pad 10->16 halves)
__device__ float4   g_h1h[MAXN * 4];        // fp16 dinv*h1 (32 halves)
__device__ int      g_idx64;
__device__ unsigned g_barc = 0;             // barrier arrive counter
__device__ volatile unsigned g_gen = 0;     // barrier generation (monotonic)

__device__ __forceinline__ float leaky(float v) {
    return v > 0.0f ? v : NEG_SLOPE * v;
}

// generation-versioned grid barrier; counter self-resets (clean per replay)
__device__ __forceinline__ void gridbar(unsigned nb) {
    __syncthreads();
    if (threadIdx.x == 0) {
        unsigned g = g_gen;
        __threadfence();
        if (atomicAdd(&g_barc, 1u) == nb - 1u) {
            g_barc = 0u;
            __threadfence();
            g_gen = g + 1u;
        } else {
            while (g_gen == g) __nanosleep(64);
        }
        __threadfence();
    }
    __syncthreads();
}

__global__ __launch_bounds__(256, 5)
void k_gcn(const float* __restrict__ x, const void* __restrict__ ei,
           const float* __restrict__ W1, const float* __restrict__ b1,
           const float* __restrict__ W2, const float* __restrict__ b2,
           const float* __restrict__ Wfc, const float* __restrict__ bfc,
           float* __restrict__ out, int N, int E) {
    __shared__ float sbuf[2560];             // phase2 staging, then W1|W2
    float* sW1 = sbuf;                       // 320 floats
    float* sW2 = sbuf + 320;                 // 2048 floats
    const unsigned nb = gridDim.x;
    const int tid = threadIdx.x;
    const int gid = blockIdx.x * 256 + tid;
    const int gstride = nb * 256;

    // ---- phase 0: zero counters; block 0 sniffs index dtype ----------------
    for (int i = gid; i < N; i += gstride) g_cnt[i] = 0;
    if (blockIdx.x == 0) {
        int w = __ldg((const int*)ei + 2 * tid + 1);  // odd words
        int any = __syncthreads_or(w != 0);
        if (tid == 0) g_idx64 = any ? 0 : 1;          // int64 hi words == 0
    }
    gridbar(nb);

    // ---- phase 1: single edge pass -> bucketed CSR -------------------------
    {
        const int is64 = g_idx64;
        if (is64) {
            const long long* p = (const long long*)ei;
            for (int e = gid; e < E; e += gstride) {
                int r = (int)__ldg(p + e);
                int t = (int)__ldg(p + E + e);
                int pos = atomicAdd(&g_cnt[t], 1);
                if (pos < BUCKET) g_csr[t * BUCKET + pos] = r;
            }
        } else {
            const int* p = (const int*)ei;
            for (int e = gid; e < E; e += gstride) {
                int r = __ldg(p + e);
                int t = __ldg(p + E + e);
                int pos = atomicAdd(&g_cnt[t], 1);
                if (pos < BUCKET) g_csr[t * BUCKET + pos] = r;
            }
        }
    }
    gridbar(nb);

    // ---- phase 2: dinv + fp16 normalized features (smem-staged, coalesced) -
    for (int base = blockIdx.x * 256; base < N; base += gstride) {
        int cnt = min(256, N - base);
        for (int idx = tid; idx < cnt * 10; idx += 256)
            sbuf[idx] = __ldg(x + base * 10 + idx);
        __syncthreads();
        int i = base + tid;
        if (tid < cnt) {
            float dv = rsqrtf((float)(g_cnt[i] + 1));
            g_dinv[i] = dv;
            const float* xr = sbuf + tid * 10;
            union { float4 f; __half2 h[4]; } u0, u1;
#pragma unroll
            for (int k = 0; k < 4; k++)
                u0.h[k] = __floats2half2_rn(dv * xr[2 * k], dv * xr[2 * k + 1]);
            u1.h[0] = __floats2half2_rn(dv * xr[8], dv * xr[9]);
            u1.h[1] = __floats2half2_rn(0.f, 0.f);
            u1.h[2] = u1.h[1]; u1.h[3] = u1.h[1];
            g_xh[i * 2] = u0.f;
            g_xh[i * 2 + 1] = u1.f;
        }
        __syncthreads();
    }
    gridbar(nb);

    // stage weights (sbuf is free now; used by phases 3/4)
    for (int idx = tid; idx < 320; idx += 256) sW1[idx] = W1[idx];
    for (int idx = tid; idx < 2048; idx += 256) sW2[idx] = W2[idx];
    __syncthreads();

    // ---- phase 3: layer 1 -- 4 nodes/warp, 8 lanes/node, unroll-4 ----------
    // lane: q = node sub (0..3), s = half2 chunk (features 2s,2s+1)
    {
        const int wg = gid >> 5, nwarp = gstride >> 5;
        const int lane = tid & 31;
        const int q = lane >> 3, s = lane & 7;
        const int qb = lane & 24;             // group base for shfl
        const __half2* xh = (const __half2*)g_xh;
        for (int i0 = wg * 4; i0 < N; i0 += nwarp * 4) {
            int i = i0 + q;
            bool act = (i < N);
            int d = act ? min(g_cnt[i], BUCKET) : 0;
            const int* row = g_csr + i * BUCKET;
            float ax = 0.0f, ay = 0.0f;
            int e = 0;
            for (; e + 3 < d; e += 4) {       // unroll-4: 4 loads in flight
                int sa = __ldg(row + e),     sb = __ldg(row + e + 1);
                int sc = __ldg(row + e + 2), sd = __ldg(row + e + 3);
                float2 va = __half22float2(xh[sa * 8 + s]);
                float2 vb = __half22float2(xh[sb * 8 + s]);
                float2 vc = __half22float2(xh[sc * 8 + s]);
                float2 vd = __half22float2(xh[sd * 8 + s]);
                ax += (va.x + vb.x) + (vc.x + vd.x);
                ay += (va.y + vb.y) + (vc.y + vd.y);
            }
            for (; e < d; e++) {
                int sr = __ldg(row + e);
                float2 v = __half22float2(xh[sr * 8 + s]);
                ax += v.x; ay += v.y;
            }
            if (act) {                        // self-loop
                float2 v = __half22float2(xh[i * 8 + s]);
                ax += v.x; ay += v.y;
            }
            float dv = act ? g_dinv[i] : 0.0f;
            // outputs 4s..4s+3
            float o0 = 0.f, o1 = 0.f, o2 = 0.f, o3 = 0.f;
#pragma unroll
            for (int k = 0; k < 10; k++) {
                float av = __shfl_sync(0xffffffffu,
                                       (k & 1) ? ay : ax, qb | (k >> 1));
                const float* w = sW1 + k * 32 + 4 * s;
                o0 += av * w[0]; o1 += av * w[1];
                o2 += av * w[2]; o3 += av * w[3];
            }
            if (act) {
                float h0 = leaky(o0 * dv + __ldg(b1 + 4 * s));
                float h1 = leaky(o1 * dv + __ldg(b1 + 4 * s + 1));
                float h2 = leaky(o2 * dv + __ldg(b1 + 4 * s + 2));
                float h3 = leaky(o3 * dv + __ldg(b1 + 4 * s + 3));
                union { uint2 u; __half2 h[2]; } pk;
                pk.h[0] = __floats2half2_rn(dv * h0, dv * h1);
                pk.h[1] = __floats2half2_rn(dv * h2, dv * h3);
                ((uint2*)g_h1h)[i * 8 + s] = pk.u;
            }
        }
    }
    gridbar(nb);

    // ---- phase 4: layer 2 + FC -- 4 nodes/warp, 8 lanes/node, unroll-2 -----
    // sub-lane s: c = s&3 (float4 chunk = features 8c..8c+7), eo = s>>2 (0/1)
    {
        const int wg = gid >> 5, nwarp = gstride >> 5;
        const int lane = tid & 31;
        const int q = lane >> 3, s = lane & 7;
        const int c = s & 3, eo = s >> 2;
        const int qb = lane & 24;
        const float4* hh = (const float4*)g_h1h;
        const float bfcv = __ldg(bfc);
        for (int i0 = wg * 4; i0 < N; i0 += nwarp * 4) {
            int i = i0 + q;
            bool act = (i < N);
            int d = act ? min(g_cnt[i], BUCKET) : 0;
            const int* row = g_csr + i * BUCKET;
            float acc[8] = {0.f, 0.f, 0.f, 0.f, 0.f, 0.f, 0.f, 0.f};
            int e = eo;
            for (; e + 2 < d; e += 4) {       // unroll-2: 2 rows in flight
                int sa = __ldg(row + e), sb = __ldg(row + e + 2);
                float4 va = hh[sa * 4 + c], vb = hh[sb * 4 + c];
                const __half2* ha = (const __half2*)&va;
                const __half2* hbp = (const __half2*)&vb;
#pragma unroll
                for (int j = 0; j < 4; j++) {
                    float2 fa = __half22float2(ha[j]);
                    float2 fb = __half22float2(hbp[j]);
                    acc[2 * j] += fa.x + fb.x;
                    acc[2 * j + 1] += fa.y + fb.y;
                }
            }
            for (; e < d; e += 2) {
                int sr = __ldg(row + e);
                float4 v = hh[sr * 4 + c];
                const __half2* hp = (const __half2*)&v;
#pragma unroll
                for (int j = 0; j < 4; j++) {
                    float2 f = __half22float2(hp[j]);
                    acc[2 * j] += f.x; acc[2 * j + 1] += f.y;
                }
            }
            if (act && eo == 0) {             // self-loop
                float4 v = hh[i * 4 + c];
                const __half2* hp = (const __half2*)&v;
#pragma unroll
                for (int j = 0; j < 4; j++) {
                    float2 f = __half22float2(hp[j]);
                    acc[2 * j] += f.x; acc[2 * j + 1] += f.y;
                }
            }
            // reduce over 2 edge groups (xor 4 stays within the 8-lane node)
#pragma unroll
            for (int j = 0; j < 8; j++)
                acc[j] += __shfl_xor_sync(0xffffffffu, acc[j], 4);
            float dv = act ? g_dinv[i] : 0.0f;
#pragma unroll
            for (int j = 0; j < 8; j++) acc[j] *= dv;
            // outputs {4s..4s+3} and {32+4s..32+4s+3}; feature kk lives in
            // lane qb|(kk>>3) register acc[kk&7]
            float p0 = 0.f, p1 = 0.f, p2 = 0.f, p3 = 0.f;
            float r0 = 0.f, r1 = 0.f, r2 = 0.f, r3 = 0.f;
#pragma unroll
            for (int kk = 0; kk < 32; kk++) {
                float av = __shfl_sync(0xffffffffu, acc[kk & 7],
                                       qb | (kk >> 3));
                const float4 w0 = *(const float4*)(sW2 + kk * 64 + 4 * s);
                const float4 w1 = *(const float4*)(sW2 + kk * 64 + 32 + 4 * s);
                p0 += av * w0.x; p1 += av * w0.y;
                p2 += av * w0.z; p3 += av * w0.w;
                r0 += av * w1.x; r1 += av * w1.y;
                r2 += av * w1.z; r3 += av * w1.w;
            }
            float sv;
            {
                float h0 = leaky(p0 + __ldg(b2 + 4 * s));
                float h1 = leaky(p1 + __ldg(b2 + 4 * s + 1));
                float h2 = leaky(p2 + __ldg(b2 + 4 * s + 2));
                float h3 = leaky(p3 + __ldg(b2 + 4 * s + 3));
                float g0 = leaky(r0 + __ldg(b2 + 32 + 4 * s));
                float g1 = leaky(r1 + __ldg(b2 + 32 + 4 * s + 1));
                float g2 = leaky(r2 + __ldg(b2 + 32 + 4 * s + 2));
                float g3 = leaky(r3 + __ldg(b2 + 32 + 4 * s + 3));
                sv = h0 * __ldg(Wfc + 10 + 4 * s)
                   + h1 * __ldg(Wfc + 10 + 4 * s + 1)
                   + h2 * __ldg(Wfc + 10 + 4 * s + 2)
                   + h3 * __ldg(Wfc + 10 + 4 * s + 3)
                   + g0 * __ldg(Wfc + 42 + 4 * s)
                   + g1 * __ldg(Wfc + 42 + 4 * s + 1)
                   + g2 * __ldg(Wfc + 42 + 4 * s + 2)
                   + g3 * __ldg(Wfc + 42 + 4 * s + 3);
            }
            if (act) {
                sv += __ldg(x + i * 10 + s) * __ldg(Wfc + s);
                if (s < 2)
                    sv += __ldg(x + i * 10 + 8 + s) * __ldg(Wfc + 8 + s);
            }
            // sum over the 8-lane node group
#pragma unroll
            for (int o = 4; o > 0; o >>= 1)
                sv += __shfl_xor_sync(0xffffffffu, sv, o);
            if (act && s == 0)
                out[i] = 1.0f / (1.0f + __expf(-(sv + bfcv)));
        }
    }
}

// ---------------------------------------------------------------------------
extern "C" void kernel_launch(void* const* d_in, const int* in_sizes, int n_in,
                              void* d_out, int out_size) {
    const float* x   = (const float*)d_in[0];
    const void*  ei  = d_in[1];
    const float* W1  = (const float*)d_in[2];
    const float* b1  = (const float*)d_in[3];
    const float* W2  = (const float*)d_in[4];
    const float* b2  = (const float*)d_in[5];
    const float* Wfc = (const float*)d_in[6];
    const float* bfc = (const float*)d_in[7];
    float* out = (float*)d_out;

    int N = in_sizes[0] / 10;
    int E = in_sizes[1] / 2;
    if (N > MAXN) N = MAXN;
    if (E > MAXE) E = MAXE;

    // grid sized so every CTA is co-resident (required by gridbar)
    int dev = 0, sms = 0, occ = 0;
    cudaGetDevice(&dev);
    cudaDeviceGetAttribute(&sms, cudaDevAttrMultiProcessorCount, dev);
    cudaOccupancyMaxActiveBlocksPerMultiprocessor(&occ, k_gcn, 256, 0);
    if (occ < 1) occ = 1;
    int grid = sms * occ;

    k_gcn<<<grid, 256>>>(x, ei, W1, b1, W2, b2, Wfc, bfc, out, N, E);
}

// round 14
// speedup vs baseline: 1.0403x; 1.0403x over previous
#include <cuda_runtime.h>
#include <cuda_fp16.h>

// ---------------------------------------------------------------------------
// GCN: 2x GCNConv (sym-norm, self-loops) + leaky + concat-FC + sigmoid
// R14: vs R12 (best config, launch_bounds(256,4) restored):
//  - phase1: explicit x4 unroll -> 4 independent atomic->store chains per
//            thread (phase was MLP=1 latency-serial on 318-cyc ATOMG)
//  - phases 3/4: int4-vectorized CSR index loads (rows 512B-aligned)
//            -> 4 index wavefronts -> 1
// ---------------------------------------------------------------------------

#define MAXN   100000
#define MAXE   1600000
#define BUCKET 128            // max in-degree per node (Poisson(16): safe)
#define NEG_SLOPE 0.01f

__device__ int      g_cnt[MAXN];            // bucket fill count == in-degree
__device__ int      g_csr[MAXN * BUCKET];   // sources, bucketed by target
__device__ float    g_dinv[MAXN];           // rsqrt(deg+1)
__device__ float4   g_xh [MAXN * 2];        // fp16 dinv*x (pad 10->16 halves)
__device__ float4   g_h1h[MAXN * 4];        // fp16 dinv*h1 (32 halves)
__device__ int      g_idx64;
__device__ unsigned g_barc = 0;             // barrier arrive counter
__device__ volatile unsigned g_gen = 0;     // barrier generation (monotonic)

__device__ __forceinline__ float leaky(float v) {
    return v > 0.0f ? v : NEG_SLOPE * v;
}

// generation-versioned grid barrier; counter self-resets (clean per replay)
__device__ __forceinline__ void gridbar(unsigned nb) {
    __syncthreads();
    if (threadIdx.x == 0) {
        unsigned g = g_gen;
        __threadfence();
        if (atomicAdd(&g_barc, 1u) == nb - 1u) {
            g_barc = 0u;
            __threadfence();
            g_gen = g + 1u;
        } else {
            while (g_gen == g) __nanosleep(64);
        }
        __threadfence();
    }
    __syncthreads();
}

__global__ __launch_bounds__(256, 4)
void k_gcn(const float* __restrict__ x, const void* __restrict__ ei,
           const float* __restrict__ W1, const float* __restrict__ b1,
           const float* __restrict__ W2, const float* __restrict__ b2,
           const float* __restrict__ Wfc, const float* __restrict__ bfc,
           float* __restrict__ out, int N, int E) {
    __shared__ float sbuf[2560];             // phase2 staging, then W1|W2
    float* sW1 = sbuf;                       // 320 floats
    float* sW2 = sbuf + 320;                 // 2048 floats
    const unsigned nb = gridDim.x;
    const int tid = threadIdx.x;
    const int gid = blockIdx.x * 256 + tid;
    const int gstride = nb * 256;

    // ---- phase 0: zero counters; block 0 sniffs index dtype ----------------
    for (int i = gid; i < N; i += gstride) g_cnt[i] = 0;
    if (blockIdx.x == 0) {
        int w = __ldg((const int*)ei + 2 * tid + 1);  // odd words
        int any = __syncthreads_or(w != 0);
        if (tid == 0) g_idx64 = any ? 0 : 1;          // int64 hi words == 0
    }
    gridbar(nb);

    // ---- phase 1: edge pass -> bucketed CSR, x4 unrolled atomic chains -----
    {
        const int is64 = g_idx64;
        if (is64) {
            const long long* p = (const long long*)ei;
            int e = gid;
            for (; e + 3 * gstride < E; e += 4 * gstride) {
                int e1 = e + gstride, e2 = e + 2 * gstride, e3 = e + 3 * gstride;
                int r0 = (int)__ldg(p + e),      t0 = (int)__ldg(p + E + e);
                int r1 = (int)__ldg(p + e1),     t1 = (int)__ldg(p + E + e1);
                int r2 = (int)__ldg(p + e2),     t2 = (int)__ldg(p + E + e2);
                int r3 = (int)__ldg(p + e3),     t3 = (int)__ldg(p + E + e3);
                int p0 = atomicAdd(&g_cnt[t0], 1);
                int p1 = atomicAdd(&g_cnt[t1], 1);
                int p2 = atomicAdd(&g_cnt[t2], 1);
                int p3 = atomicAdd(&g_cnt[t3], 1);
                if (p0 < BUCKET) g_csr[t0 * BUCKET + p0] = r0;
                if (p1 < BUCKET) g_csr[t1 * BUCKET + p1] = r1;
                if (p2 < BUCKET) g_csr[t2 * BUCKET + p2] = r2;
                if (p3 < BUCKET) g_csr[t3 * BUCKET + p3] = r3;
            }
            for (; e < E; e += gstride) {
                int r = (int)__ldg(p + e);
                int t = (int)__ldg(p + E + e);
                int pos = atomicAdd(&g_cnt[t], 1);
                if (pos < BUCKET) g_csr[t * BUCKET + pos] = r;
            }
        } else {
            const int* p = (const int*)ei;
            int e = gid;
            for (; e + 3 * gstride < E; e += 4 * gstride) {
                int e1 = e + gstride, e2 = e + 2 * gstride, e3 = e + 3 * gstride;
                int r0 = __ldg(p + e),      t0 = __ldg(p + E + e);
                int r1 = __ldg(p + e1),     t1 = __ldg(p + E + e1);
                int r2 = __ldg(p + e2),     t2 = __ldg(p + E + e2);
                int r3 = __ldg(p + e3),     t3 = __ldg(p + E + e3);
                int p0 = atomicAdd(&g_cnt[t0], 1);
                int p1 = atomicAdd(&g_cnt[t1], 1);
                int p2 = atomicAdd(&g_cnt[t2], 1);
                int p3 = atomicAdd(&g_cnt[t3], 1);
                if (p0 < BUCKET) g_csr[t0 * BUCKET + p0] = r0;
                if (p1 < BUCKET) g_csr[t1 * BUCKET + p1] = r1;
                if (p2 < BUCKET) g_csr[t2 * BUCKET + p2] = r2;
                if (p3 < BUCKET) g_csr[t3 * BUCKET + p3] = r3;
            }
            for (; e < E; e += gstride) {
                int r = __ldg(p + e);
                int t = __ldg(p + E + e);
                int pos = atomicAdd(&g_cnt[t], 1);
                if (pos < BUCKET) g_csr[t * BUCKET + pos] = r;
            }
        }
    }
    gridbar(nb);

    // ---- phase 2: dinv + fp16 normalized features (smem-staged, coalesced) -
    for (int base = blockIdx.x * 256; base < N; base += gstride) {
        int cnt = min(256, N - base);
        for (int idx = tid; idx < cnt * 10; idx += 256)
            sbuf[idx] = __ldg(x + base * 10 + idx);
        __syncthreads();
        int i = base + tid;
        if (tid < cnt) {
            float dv = rsqrtf((float)(g_cnt[i] + 1));
            g_dinv[i] = dv;
            const float* xr = sbuf + tid * 10;
            union { float4 f; __half2 h[4]; } u0, u1;
#pragma unroll
            for (int k = 0; k < 4; k++)
                u0.h[k] = __floats2half2_rn(dv * xr[2 * k], dv * xr[2 * k + 1]);
            u1.h[0] = __floats2half2_rn(dv * xr[8], dv * xr[9]);
            u1.h[1] = __floats2half2_rn(0.f, 0.f);
            u1.h[2] = u1.h[1]; u1.h[3] = u1.h[1];
            g_xh[i * 2] = u0.f;
            g_xh[i * 2 + 1] = u1.f;
        }
        __syncthreads();
    }
    gridbar(nb);

    // stage weights (sbuf is free now; used by phases 3/4)
    for (int idx = tid; idx < 320; idx += 256) sW1[idx] = W1[idx];
    for (int idx = tid; idx < 2048; idx += 256) sW2[idx] = W2[idx];
    __syncthreads();

    // ---- phase 3: layer 1 -- 4 nodes/warp, 8 lanes/node, int4 idx loads ----
    // lane: q = node sub (0..3), s = half2 chunk (features 2s,2s+1)
    {
        const int wg = gid >> 5, nwarp = gstride >> 5;
        const int lane = tid & 31;
        const int q = lane >> 3, s = lane & 7;
        const int qb = lane & 24;             // group base for shfl
        const __half2* xh = (const __half2*)g_xh;
        for (int i0 = wg * 4; i0 < N; i0 += nwarp * 4) {
            int i = i0 + q;
            bool act = (i < N);
            int d = act ? min(g_cnt[i], BUCKET) : 0;
            const int* row = g_csr + i * BUCKET;
            const int4* row4 = (const int4*)row;
            float ax = 0.0f, ay = 0.0f;
            int e = 0;
            for (; e + 3 < d; e += 4) {       // 1 idx wavefront, 4 gathers
                int4 qd = __ldg(row4 + (e >> 2));
                float2 va = __half22float2(xh[qd.x * 8 + s]);
                float2 vb = __half22float2(xh[qd.y * 8 + s]);
                float2 vc = __half22float2(xh[qd.z * 8 + s]);
                float2 vd = __half22float2(xh[qd.w * 8 + s]);
                ax += (va.x + vb.x) + (vc.x + vd.x);
                ay += (va.y + vb.y) + (vc.y + vd.y);
            }
            for (; e < d; e++) {
                int sr = __ldg(row + e);
                float2 v = __half22float2(xh[sr * 8 + s]);
                ax += v.x; ay += v.y;
            }
            if (act) {                        // self-loop
                float2 v = __half22float2(xh[i * 8 + s]);
                ax += v.x; ay += v.y;
            }
            float dv = act ? g_dinv[i] : 0.0f;
            // outputs 4s..4s+3
            float o0 = 0.f, o1 = 0.f, o2 = 0.f, o3 = 0.f;
#pragma unroll
            for (int k = 0; k < 10; k++) {
                float av = __shfl_sync(0xffffffffu,
                                       (k & 1) ? ay : ax, qb | (k >> 1));
                const float* w = sW1 + k * 32 + 4 * s;
                o0 += av * w[0]; o1 += av * w[1];
                o2 += av * w[2]; o3 += av * w[3];
            }
            if (act) {
                float h0 = leaky(o0 * dv + __ldg(b1 + 4 * s));
                float h1 = leaky(o1 * dv + __ldg(b1 + 4 * s + 1));
                float h2 = leaky(o2 * dv + __ldg(b1 + 4 * s + 2));
                float h3 = leaky(o3 * dv + __ldg(b1 + 4 * s + 3));
                union { uint2 u; __half2 h[2]; } pk;
                pk.h[0] = __floats2half2_rn(dv * h0, dv * h1);
                pk.h[1] = __floats2half2_rn(dv * h2, dv * h3);
                ((uint2*)g_h1h)[i * 8 + s] = pk.u;
            }
        }
    }
    gridbar(nb);

    // ---- phase 4: layer 2 + FC -- 4 nodes/warp, 8 lanes/node ---------------
    // sub-lane s: c = s&3 (float4 chunk = features 8c..8c+7), eo = s>>2 (0/1)
    // int4 idx load covers 4 edges; eo=0 takes .x/.z, eo=1 takes .y/.w
    {
        const int wg = gid >> 5, nwarp = gstride >> 5;
        const int lane = tid & 31;
        const int q = lane >> 3, s = lane & 7;
        const int c = s & 3, eo = s >> 2;
        const int qb = lane & 24;
        const float4* hh = (const float4*)g_h1h;
        const float bfcv = __ldg(bfc);
        for (int i0 = wg * 4; i0 < N; i0 += nwarp * 4) {
            int i = i0 + q;
            bool act = (i < N);
            int d = act ? min(g_cnt[i], BUCKET) : 0;
            const int* row = g_csr + i * BUCKET;
            const int4* row4 = (const int4*)row;
            float acc[8] = {0.f, 0.f, 0.f, 0.f, 0.f, 0.f, 0.f, 0.f};
            int m = 0;
            for (; 4 * m + 3 < d; m++) {      // 4 edges per int4, 2 per group
                int4 qd = __ldg(row4 + m);
                int sa = eo ? qd.y : qd.x;
                int sb = eo ? qd.w : qd.z;
                float4 va = hh[sa * 4 + c], vb = hh[sb * 4 + c];
                const __half2* ha = (const __half2*)&va;
                const __half2* hbp = (const __half2*)&vb;
#pragma unroll
                for (int j = 0; j < 4; j++) {
                    float2 fa = __half22float2(ha[j]);
                    float2 fb = __half22float2(hbp[j]);
                    acc[2 * j] += fa.x + fb.x;
                    acc[2 * j + 1] += fa.y + fb.y;
                }
            }
            for (int e = 4 * m + eo; e < d; e += 2) {   // tail (<=2 iters)
                int sr = __ldg(row + e);
                float4 v = hh[sr * 4 + c];
                const __half2* hp = (const __half2*)&v;
#pragma unroll
                for (int j = 0; j < 4; j++) {
                    float2 f = __half22float2(hp[j]);
                    acc[2 * j] += f.x; acc[2 * j + 1] += f.y;
                }
            }
            if (act && eo == 0) {             // self-loop
                float4 v = hh[i * 4 + c];
                const __half2* hp = (const __half2*)&v;
#pragma unroll
                for (int j = 0; j < 4; j++) {
                    float2 f = __half22float2(hp[j]);
                    acc[2 * j] += f.x; acc[2 * j + 1] += f.y;
                }
            }
            // reduce over 2 edge groups (xor 4 stays within the 8-lane node)
#pragma unroll
            for (int j = 0; j < 8; j++)
                acc[j] += __shfl_xor_sync(0xffffffffu, acc[j], 4);
            float dv = act ? g_dinv[i] : 0.0f;
#pragma unroll
            for (int j = 0; j < 8; j++) acc[j] *= dv;
            // outputs {4s..4s+3} and {32+4s..32+4s+3}; feature kk lives in
            // lane qb|(kk>>3) register acc[kk&7]
            float p0 = 0.f, p1 = 0.f, p2 = 0.f, p3 = 0.f;
            float r0 = 0.f, r1 = 0.f, r2 = 0.f, r3 = 0.f;
#pragma unroll
            for (int kk = 0; kk < 32; kk++) {
                float av = __shfl_sync(0xffffffffu, acc[kk & 7],
                                       qb | (kk >> 3));
                const float4 w0 = *(const float4*)(sW2 + kk * 64 + 4 * s);
                const float4 w1 = *(const float4*)(sW2 + kk * 64 + 32 + 4 * s);
                p0 += av * w0.x; p1 += av * w0.y;
                p2 += av * w0.z; p3 += av * w0.w;
                r0 += av * w1.x; r1 += av * w1.y;
                r2 += av * w1.z; r3 += av * w1.w;
            }
            float sv;
            {
                float h0 = leaky(p0 + __ldg(b2 + 4 * s));
                float h1 = leaky(p1 + __ldg(b2 + 4 * s + 1));
                float h2 = leaky(p2 + __ldg(b2 + 4 * s + 2));
                float h3 = leaky(p3 + __ldg(b2 + 4 * s + 3));
                float g0 = leaky(r0 + __ldg(b2 + 32 + 4 * s));
                float g1 = leaky(r1 + __ldg(b2 + 32 + 4 * s + 1));
                float g2 = leaky(r2 + __ldg(b2 + 32 + 4 * s + 2));
                float g3 = leaky(r3 + __ldg(b2 + 32 + 4 * s + 3));
                sv = h0 * __ldg(Wfc + 10 + 4 * s)
                   + h1 * __ldg(Wfc + 10 + 4 * s + 1)
                   + h2 * __ldg(Wfc + 10 + 4 * s + 2)
                   + h3 * __ldg(Wfc + 10 + 4 * s + 3)
                   + g0 * __ldg(Wfc + 42 + 4 * s)
                   + g1 * __ldg(Wfc + 42 + 4 * s + 1)
                   + g2 * __ldg(Wfc + 42 + 4 * s + 2)
                   + g3 * __ldg(Wfc + 42 + 4 * s + 3);
            }
            if (act) {
                sv += __ldg(x + i * 10 + s) * __ldg(Wfc + s);
                if (s < 2)
                    sv += __ldg(x + i * 10 + 8 + s) * __ldg(Wfc + 8 + s);
            }
            // sum over the 8-lane node group
#pragma unroll
            for (int o = 4; o > 0; o >>= 1)
                sv += __shfl_xor_sync(0xffffffffu, sv, o);
            if (act && s == 0)
                out[i] = 1.0f / (1.0f + __expf(-(sv + bfcv)));
        }
    }
}

// ---------------------------------------------------------------------------
extern "C" void kernel_launch(void* const* d_in, const int* in_sizes, int n_in,
                              void* d_out, int out_size) {
    const float* x   = (const float*)d_in[0];
    const void*  ei  = d_in[1];
    const float* W1  = (const float*)d_in[2];
    const float* b1  = (const float*)d_in[3];
    const float* W2  = (const float*)d_in[4];
    const float* b2  = (const float*)d_in[5];
    const float* Wfc = (const float*)d_in[6];
    const float* bfc = (const float*)d_in[7];
    float* out = (float*)d_out;

    int N = in_sizes[0] / 10;
    int E = in_sizes[1] / 2;
    if (N > MAXN) N = MAXN;
    if (E > MAXE) E = MAXE;

    // grid sized so every CTA is co-resident (required by gridbar)
    int dev = 0, sms = 0, occ = 0;
    cudaGetDevice(&dev);
    cudaDeviceGetAttribute(&sms, cudaDevAttrMultiProcessorCount, dev);
    cudaOccupancyMaxActiveBlocksPerMultiprocessor(&occ, k_gcn, 256, 0);
    if (occ < 1) occ = 1;
    int grid = sms * occ;

    k_gcn<<<grid, 256>>>(x, ei, W1, b1, W2, b2, Wfc, bfc, out, N, E);
}